// round 13
// baseline (speedup 1.0000x reference)
#include <cuda_runtime.h>
#include <cuda_fp16.h>
#include <math.h>

constexpr int N_ = 65536;
constexpr int K_ = 64;
constexpr int G_ = 16;
constexpr int NC_ = G_ * G_ * G_;
constexpr unsigned NM_ = N_ - 1;    // power-of-two mask

// ---------------- device scratch ----------------
__device__ uint4 g_t1h[N_];          // fp16 rows: 8 halves  = 16B (orig index space)
__device__ uint4 g_t2h[N_ * 2];      // fp16 rows: 16 halves = 32B
__device__ uint4 g_t3h[N_ * 4];      // fp16 rows: 32 halves = 64B
__device__ __align__(16) float g_pos4[N_ * 4];
__device__ int g_nbr[N_ * K_];
__device__ int g_perm[N_];           // processing order: sorted slot -> orig index
__device__ unsigned short g_cid[N_];
__device__ int g_hist[NC_];
__device__ int g_cursor[NC_];
__device__ int g_idx_is64;

__device__ __forceinline__ float celu1(float x) {
    return x > 0.0f ? x : expm1f(x);
}

__device__ __forceinline__ void fmax8(float* m, uint4 u) {
    __half2* h = (__half2*)&u;
#pragma unroll
    for (int q = 0; q < 4; q++) {
        float2 f = __half22float2(h[q]);
        m[2 * q]     = fmaxf(m[2 * q], f.x);
        m[2 * q + 1] = fmaxf(m[2 * q + 1], f.y);
    }
}

__device__ __forceinline__ uint4 pack8(const float* v) {
    uint4 u;
    __half2* h = (__half2*)&u;
#pragma unroll
    for (int q = 0; q < 4; q++)
        h[q] = __floats2half2_rn(v[2 * q], v[2 * q + 1]);
    return u;
}

__device__ __forceinline__ uint2 pack4(const float* v) {
    uint2 u;
    __half2* h = (__half2*)&u;
    h[0] = __floats2half2_rn(v[0], v[1]);
    h[1] = __floats2half2_rn(v[2], v[3]);
    return u;
}

// ---------------- K0: dtype detect + zero hist ----------------
__global__ void detect_kernel(const void* __restrict__ idx_raw)
{
    for (int c = threadIdx.x; c < NC_; c += blockDim.x) g_hist[c] = 0;
    if (threadIdx.x == 0) {
        const long long* p = (const long long*)idx_raw;
        const long long mid = 1 << 20;
        int ok = 1;
        for (int t = 0; t < 32; t++) {
            long long v = p[mid + t];
            if (v < 0 || v >= N_) { ok = 0; break; }
        }
        g_idx_is64 = ok;
    }
}

// ---------------- K1: prep — idx convert, pos4, t1, cell hist, out pos copy ----------------
__global__ void prep_kernel(const float* __restrict__ pos,
                            const void* __restrict__ idx_raw,
                            const float* __restrict__ w1a,
                            float* __restrict__ out, int out_size)
{
    const int stride = gridDim.x * blockDim.x;
    const int tid = blockIdx.x * blockDim.x + threadIdx.x;

    if (g_idx_is64) {
        const long long* p = (const long long*)idx_raw;
        for (int e = tid; e < N_ * K_; e += stride)
            g_nbr[e] = ((int)p[e]) & NM_;
    } else {
        const int* p = (const int*)idx_raw;
        for (int e = tid; e < N_ * K_; e += stride)
            g_nbr[e] = p[e] & NM_;
    }

    for (int i = tid; i < N_; i += stride) {
        float p0 = pos[i * 3 + 0], p1 = pos[i * 3 + 1], p2 = pos[i * 3 + 2];
        *reinterpret_cast<float4*>(g_pos4 + i * 4) = make_float4(p0, p1, p2, 0.0f);
        float t[8];
#pragma unroll
        for (int c = 0; c < 8; c++) {
            t[c] = p0 * (w1a[0 * 8 + c] + w1a[3 * 8 + c])
                 + p1 * (w1a[1 * 8 + c] + w1a[4 * 8 + c])
                 + p2 * (w1a[2 * 8 + c] + w1a[5 * 8 + c]);
        }
        g_t1h[i] = pack8(t);

        int cx = min(G_ - 1, max(0, (int)(p0 * 16.0f)));
        int cy = min(G_ - 1, max(0, (int)(p1 * 16.0f)));
        int cz = min(G_ - 1, max(0, (int)(p2 * 16.0f)));
        int cid = (cx * G_ + cy) * G_ + cz;
        g_cid[i] = (unsigned short)cid;
        atomicAdd(&g_hist[cid], 1);
    }

    for (int e = tid; e < 3 * N_; e += stride) out[e] = pos[e];
    for (int e = 35 * N_ + tid; e < out_size; e += stride) out[e] = 0.0f;
}

// ---------------- K2: exclusive scan of 4096 counts, single warp ----------------
__global__ void scan_kernel()
{
    const int lane = threadIdx.x;
    const int base = lane * (NC_ / 32);
    int s = 0;
    for (int c = 0; c < NC_ / 32; c++) s += g_hist[base + c];
    int incl = s;
#pragma unroll
    for (int off = 1; off < 32; off <<= 1) {
        int x = __shfl_up_sync(0xffffffffu, incl, off);
        if (lane >= off) incl += x;
    }
    int run = incl - s;
    for (int c = 0; c < NC_ / 32; c++) {
        g_cursor[base + c] = run;
        run += g_hist[base + c];
    }
}

// ---------------- K3: scatter — build processing order ----------------
__global__ void scatter_kernel()
{
    const int stride = gridDim.x * blockDim.x;
    const int tid = blockIdx.x * blockDim.x + threadIdx.x;
    for (int i = tid; i < N_; i += stride) {
        int s = atomicAdd(&g_cursor[g_cid[i]], 1) & NM_;
        g_perm[s] = i;
    }
}

// ---------------- Layer 1: t1(F=8) -> t2(FN=16); 4 threads/point, sorted processing order ----------------
__global__ void __launch_bounds__(256)
layer1_kernel(const float* __restrict__ w1a, const float* __restrict__ b1a,
              const float* __restrict__ w1b, const float* __restrict__ b1b,
              const float* __restrict__ w2a)
{
    __shared__ float s_wad[24];
    __shared__ float s_ba[8];
    __shared__ float s_wb[64];
    __shared__ float s_bb[8];
    __shared__ float s_wa2[11 * 16];

    if (threadIdx.x < 24) s_wad[threadIdx.x] = w1a[24 + threadIdx.x];
    if (threadIdx.x < 8)  s_ba[threadIdx.x] = b1a[threadIdx.x];
    if (threadIdx.x < 64) s_wb[threadIdx.x] = w1b[threadIdx.x];
    if (threadIdx.x >= 64 && threadIdx.x < 72) s_bb[threadIdx.x - 64] = b1b[threadIdx.x - 64];
    if (threadIdx.x < 176) s_wa2[threadIdx.x] = w2a[threadIdx.x];
    __syncthreads();

    const int s = threadIdx.x & 3;
    const int pl = threadIdx.x >> 2;
    const int i = g_perm[blockIdx.x * 64 + pl] & NM_;   // orig index, sorted order

    const float4 pp = *reinterpret_cast<const float4*>(g_pos4 + i * 4);
    const int* np = g_nbr + (size_t)i * K_;

    float m[8];
#pragma unroll
    for (int q = 0; q < 8; q++) m[q] = -1e30f;

    const int kbeg = s * 16;
    bool active = true;
#pragma unroll 8
    for (int kk = 0; kk < 16; kk++) {
        int k = kbeg + kk;
        int j = __ldg(np + k) & NM_;
        if (k > 0 && j == i) active = false;
        if (active) fmax8(m, __ldg(g_t1h + j));
    }
#pragma unroll
    for (int off = 1; off < 4; off <<= 1)
#pragma unroll
        for (int q = 0; q < 8; q++)
            m[q] = fmaxf(m[q], __shfl_xor_sync(0xffffffffu, m[q], off));

    float a[8];
#pragma unroll
    for (int q = 0; q < 8; q++) {
        float v = pp.x * s_wad[q] + pp.y * s_wad[8 + q] + pp.z * s_wad[16 + q];
        a[q] = celu1(m[q] - v + s_ba[q]);
    }

    float y[8];
#pragma unroll
    for (int q = 0; q < 8; q++) y[q] = s_bb[q];
#pragma unroll
    for (int in = 0; in < 8; in++)
#pragma unroll
        for (int q = 0; q < 8; q++) y[q] = fmaf(a[in], s_wb[in * 8 + q], y[q]);
#pragma unroll
    for (int q = 0; q < 8; q++) y[q] = celu1(y[q]);

    const int oc = s * 4;
    float acc[4] = {0.f, 0.f, 0.f, 0.f};
#pragma unroll
    for (int in = 0; in < 8; in++)
#pragma unroll
        for (int q = 0; q < 4; q++) acc[q] = fmaf(y[in], s_wa2[in * 16 + oc + q], acc[q]);
    float pv[3] = {pp.x, pp.y, pp.z};
#pragma unroll
    for (int d = 0; d < 3; d++)
#pragma unroll
        for (int q = 0; q < 4; q++) acc[q] = fmaf(pv[d], s_wa2[(8 + d) * 16 + oc + q], acc[q]);

    reinterpret_cast<uint2*>(g_t2h)[i * 4 + s] = pack4(acc);   // write at orig index
}

// ---------------- Layer 2: t2(F=16) -> t3(FN=32); 4 threads/point ----------------
__global__ void __launch_bounds__(256)
layer2_kernel(const float* __restrict__ w2a, const float* __restrict__ b2a,
              const float* __restrict__ w2b, const float* __restrict__ b2b,
              const float* __restrict__ w3a)
{
    __shared__ float s_wb[256];
    __shared__ float s_wa2[19 * 32];
    __shared__ __align__(16) float s_a[64 * 17];

    if (threadIdx.x < 256) s_wb[threadIdx.x] = w2b[threadIdx.x];
    for (int k = threadIdx.x; k < 19 * 32; k += 256) s_wa2[k] = w3a[k];
    __syncthreads();

    const int s = threadIdx.x & 3;
    const int pl = threadIdx.x >> 2;
    const int i = g_perm[blockIdx.x * 64 + pl] & NM_;
    const int c = s & 1;
    const int h = s >> 1;

    const float4 pp = *reinterpret_cast<const float4*>(g_pos4 + i * 4);
    const int* np = g_nbr + (size_t)i * K_;
    const float* wa_d = w2a + 8 * 16;
    float* row = s_a + pl * 17;

    float m[8];
#pragma unroll
    for (int q = 0; q < 8; q++) m[q] = -1e30f;

    const int kbeg = h * 32;
    bool active = true;
#pragma unroll 8
    for (int kk = 0; kk < 32; kk++) {
        int k = kbeg + kk;
        int j = __ldg(np + k) & NM_;
        if (k > 0 && j == i) active = false;
        if (active) fmax8(m, __ldg(g_t2h + j * 2 + c));
    }
#pragma unroll
    for (int q = 0; q < 8; q++)
        m[q] = fmaxf(m[q], __shfl_xor_sync(0xffffffffu, m[q], 2));

#pragma unroll
    for (int q = 0; q < 8; q++) row[c * 8 + q] = m[q];
    __syncwarp();

    const int col = s * 4;
    float a[4];
#pragma unroll
    for (int q = 0; q < 4; q++) {
        float mm = row[col + q];
        float v = pp.x * wa_d[col + q] + pp.y * wa_d[16 + col + q] + pp.z * wa_d[32 + col + q];
        a[q] = celu1(mm - v + b2a[col + q]);
    }
#pragma unroll
    for (int q = 0; q < 4; q++) row[col + q] = a[q];
    __syncwarp();

    float y[4];
#pragma unroll
    for (int q = 0; q < 4; q++) y[q] = b2b[col + q];
#pragma unroll
    for (int in = 0; in < 16; in++) {
        float av = row[in];
#pragma unroll
        for (int q = 0; q < 4; q++) y[q] = fmaf(av, s_wb[in * 16 + col + q], y[q]);
    }
#pragma unroll
    for (int q = 0; q < 4; q++) y[q] = celu1(y[q]);
    __syncwarp();
#pragma unroll
    for (int q = 0; q < 4; q++) row[col + q] = y[q];
    __syncwarp();

    const int oc = s * 8;
    float acc[8];
#pragma unroll
    for (int q = 0; q < 8; q++) acc[q] = 0.0f;
#pragma unroll
    for (int in = 0; in < 16; in++) {
        float yv = row[in];
#pragma unroll
        for (int q = 0; q < 8; q++) acc[q] = fmaf(yv, s_wa2[in * 32 + oc + q], acc[q]);
    }
    float pv[3] = {pp.x, pp.y, pp.z};
#pragma unroll
    for (int d = 0; d < 3; d++)
#pragma unroll
        for (int q = 0; q < 8; q++) acc[q] = fmaf(pv[d], s_wa2[(16 + d) * 32 + oc + q], acc[q]);

    g_t3h[i * 4 + s] = pack8(acc);
}

// ---------------- Layer 3: t3(F=32) -> out(fp32); 8 threads/point ----------------
__global__ void __launch_bounds__(256)
layer3_kernel(const float* __restrict__ w3a, const float* __restrict__ b3a,
              const float* __restrict__ w3b, const float* __restrict__ b3b,
              float* __restrict__ out_feat)
{
    __shared__ float s_wb[1024];
    __shared__ __align__(16) float s_a[32 * 33];

    for (int k = threadIdx.x; k < 1024; k += 256) s_wb[k] = w3b[k];
    __syncthreads();

    const int s = threadIdx.x & 7;
    const int pl = threadIdx.x >> 3;
    const int i = g_perm[blockIdx.x * 32 + pl] & NM_;
    const int c = s & 3;
    const int h = s >> 2;

    const float4 pp = *reinterpret_cast<const float4*>(g_pos4 + i * 4);
    const int* np = g_nbr + (size_t)i * K_;
    const float* wa_d = w3a + 16 * 32;
    float* row = s_a + pl * 33;

    float m[8];
#pragma unroll
    for (int q = 0; q < 8; q++) m[q] = -1e30f;

    const int kbeg = h * 32;
    bool active = true;
#pragma unroll 8
    for (int kk = 0; kk < 32; kk++) {
        int k = kbeg + kk;
        int j = __ldg(np + k) & NM_;
        if (k > 0 && j == i) active = false;
        if (active) fmax8(m, __ldg(g_t3h + j * 4 + c));
    }
#pragma unroll
    for (int q = 0; q < 8; q++)
        m[q] = fmaxf(m[q], __shfl_xor_sync(0xffffffffu, m[q], 4));

#pragma unroll
    for (int q = 0; q < 8; q++) row[c * 8 + q] = m[q];
    __syncwarp();

    const int col = s * 4;
    float a[4];
#pragma unroll
    for (int q = 0; q < 4; q++) {
        float mm = row[col + q];
        float v = pp.x * wa_d[col + q] + pp.y * wa_d[32 + col + q] + pp.z * wa_d[64 + col + q];
        a[q] = celu1(mm - v + b3a[col + q]);
    }
#pragma unroll
    for (int q = 0; q < 4; q++) row[col + q] = a[q];
    __syncwarp();

    float y[4];
#pragma unroll
    for (int q = 0; q < 4; q++) y[q] = b3b[col + q];
#pragma unroll
    for (int in = 0; in < 32; in++) {
        float av = row[in];
#pragma unroll
        for (int q = 0; q < 4; q++) y[q] = fmaf(av, s_wb[in * 32 + col + q], y[q]);
    }
#pragma unroll
    for (int q = 0; q < 4; q++) y[q] = celu1(y[q]);

    *reinterpret_cast<float4*>(out_feat + (size_t)i * 32 + col) =
        make_float4(y[0], y[1], y[2], y[3]);
}

extern "C" void kernel_launch(void* const* d_in, const int* in_sizes, int n_in,
                              void* d_out, int out_size)
{
    const float* pos = (const float*)d_in[0];
    const void* in_index = d_in[4];
    const float* w1a = (const float*)d_in[5];
    const float* b1a = (const float*)d_in[6];
    const float* w1b = (const float*)d_in[7];
    const float* b1b = (const float*)d_in[8];
    const float* w2a = (const float*)d_in[9];
    const float* b2a = (const float*)d_in[10];
    const float* w2b = (const float*)d_in[11];
    const float* b2b = (const float*)d_in[12];
    const float* w3a = (const float*)d_in[13];
    const float* b3a = (const float*)d_in[14];
    const float* w3b = (const float*)d_in[15];
    const float* b3b = (const float*)d_in[16];
    float* out = (float*)d_out;

    detect_kernel<<<1, 256>>>(in_index);
    prep_kernel<<<2048, 256>>>(pos, in_index, w1a, out, out_size);
    scan_kernel<<<1, 32>>>();
    scatter_kernel<<<512, 256>>>();

    layer1_kernel<<<N_ / 64, 256>>>(w1a, b1a, w1b, b1b, w2a);
    layer2_kernel<<<N_ / 64, 256>>>(w2a, b2a, w2b, b2b, w3a);
    layer3_kernel<<<N_ / 32, 256>>>(w3a, b3a, w3b, b3b, out + 3 * N_);
}

// round 14
// speedup vs baseline: 1.0002x; 1.0002x over previous
#include <cuda_runtime.h>
#include <cuda_fp16.h>
#include <math.h>

constexpr int N_ = 65536;
constexpr int K_ = 64;
constexpr int G_ = 16;
constexpr int NC_ = G_ * G_ * G_;
constexpr unsigned NM_ = N_ - 1;    // power-of-two mask

// ---------------- device scratch ----------------
__device__ uint4 g_t1h[N_];          // fp16 rows: 8 halves  = 16B (orig index space)
__device__ uint4 g_t2h[N_ * 2];      // fp16 rows: 16 halves = 32B
__device__ uint4 g_t3h[N_ * 4];      // fp16 rows: 32 halves = 64B
__device__ __align__(16) float g_pos4[N_ * 4];
__device__ int g_nbr[N_ * K_];
__device__ int g_perm[N_];           // processing order: sorted slot -> orig index
__device__ unsigned short g_cid[N_];
__device__ int g_hist[NC_];
__device__ int g_cursor[NC_];
__device__ int g_idx_is64;

__device__ __forceinline__ float celu1(float x) {
    return x > 0.0f ? x : expm1f(x);
}

__device__ __forceinline__ void fmax8(float* m, uint4 u) {
    __half2* h = (__half2*)&u;
#pragma unroll
    for (int q = 0; q < 4; q++) {
        float2 f = __half22float2(h[q]);
        m[2 * q]     = fmaxf(m[2 * q], f.x);
        m[2 * q + 1] = fmaxf(m[2 * q + 1], f.y);
    }
}

__device__ __forceinline__ uint4 pack8(const float* v) {
    uint4 u;
    __half2* h = (__half2*)&u;
#pragma unroll
    for (int q = 0; q < 4; q++)
        h[q] = __floats2half2_rn(v[2 * q], v[2 * q + 1]);
    return u;
}

__device__ __forceinline__ uint2 pack4(const float* v) {
    uint2 u;
    __half2* h = (__half2*)&u;
    h[0] = __floats2half2_rn(v[0], v[1]);
    h[1] = __floats2half2_rn(v[2], v[3]);
    return u;
}

// ---------------- K0: dtype detect + zero hist ----------------
__global__ void detect_kernel(const void* __restrict__ idx_raw)
{
    for (int c = threadIdx.x; c < NC_; c += blockDim.x) g_hist[c] = 0;
    if (threadIdx.x == 0) {
        const long long* p = (const long long*)idx_raw;
        const long long mid = 1 << 20;
        int ok = 1;
        for (int t = 0; t < 32; t++) {
            long long v = p[mid + t];
            if (v < 0 || v >= N_) { ok = 0; break; }
        }
        g_idx_is64 = ok;
    }
}

// ---------------- K1: prep — idx convert, pos4, t1, cell hist, out pos copy ----------------
__global__ void prep_kernel(const float* __restrict__ pos,
                            const void* __restrict__ idx_raw,
                            const float* __restrict__ w1a,
                            float* __restrict__ out, int out_size)
{
    const int stride = gridDim.x * blockDim.x;
    const int tid = blockIdx.x * blockDim.x + threadIdx.x;

    if (g_idx_is64) {
        const long long* p = (const long long*)idx_raw;
        for (int e = tid; e < N_ * K_; e += stride)
            g_nbr[e] = ((int)p[e]) & NM_;
    } else {
        const int* p = (const int*)idx_raw;
        for (int e = tid; e < N_ * K_; e += stride)
            g_nbr[e] = p[e] & NM_;
    }

    for (int i = tid; i < N_; i += stride) {
        float p0 = pos[i * 3 + 0], p1 = pos[i * 3 + 1], p2 = pos[i * 3 + 2];
        *reinterpret_cast<float4*>(g_pos4 + i * 4) = make_float4(p0, p1, p2, 0.0f);
        float t[8];
#pragma unroll
        for (int c = 0; c < 8; c++) {
            t[c] = p0 * (w1a[0 * 8 + c] + w1a[3 * 8 + c])
                 + p1 * (w1a[1 * 8 + c] + w1a[4 * 8 + c])
                 + p2 * (w1a[2 * 8 + c] + w1a[5 * 8 + c]);
        }
        g_t1h[i] = pack8(t);

        int cx = min(G_ - 1, max(0, (int)(p0 * 16.0f)));
        int cy = min(G_ - 1, max(0, (int)(p1 * 16.0f)));
        int cz = min(G_ - 1, max(0, (int)(p2 * 16.0f)));
        int cid = (cx * G_ + cy) * G_ + cz;
        g_cid[i] = (unsigned short)cid;
        atomicAdd(&g_hist[cid], 1);
    }

    for (int e = tid; e < 3 * N_; e += stride) out[e] = pos[e];
    for (int e = 35 * N_ + tid; e < out_size; e += stride) out[e] = 0.0f;
}

// ---------------- K2: exclusive scan of 4096 counts, single warp ----------------
__global__ void scan_kernel()
{
    const int lane = threadIdx.x;
    const int base = lane * (NC_ / 32);
    int s = 0;
    for (int c = 0; c < NC_ / 32; c++) s += g_hist[base + c];
    int incl = s;
#pragma unroll
    for (int off = 1; off < 32; off <<= 1) {
        int x = __shfl_up_sync(0xffffffffu, incl, off);
        if (lane >= off) incl += x;
    }
    int run = incl - s;
    for (int c = 0; c < NC_ / 32; c++) {
        g_cursor[base + c] = run;
        run += g_hist[base + c];
    }
}

// ---------------- K3: scatter — build processing order ----------------
__global__ void scatter_kernel()
{
    const int stride = gridDim.x * blockDim.x;
    const int tid = blockIdx.x * blockDim.x + threadIdx.x;
    for (int i = tid; i < N_; i += stride) {
        int s = atomicAdd(&g_cursor[g_cid[i]], 1) & NM_;
        g_perm[s] = i;
    }
}

// ---------------- Layer 1: t1(F=8) -> t2(FN=16); 4 threads/point, sorted processing order ----------------
__global__ void __launch_bounds__(256)
layer1_kernel(const float* __restrict__ w1a, const float* __restrict__ b1a,
              const float* __restrict__ w1b, const float* __restrict__ b1b,
              const float* __restrict__ w2a)
{
    __shared__ float s_wad[24];
    __shared__ float s_ba[8];
    __shared__ float s_wb[64];
    __shared__ float s_bb[8];
    __shared__ float s_wa2[11 * 16];

    if (threadIdx.x < 24) s_wad[threadIdx.x] = w1a[24 + threadIdx.x];
    if (threadIdx.x < 8)  s_ba[threadIdx.x] = b1a[threadIdx.x];
    if (threadIdx.x < 64) s_wb[threadIdx.x] = w1b[threadIdx.x];
    if (threadIdx.x >= 64 && threadIdx.x < 72) s_bb[threadIdx.x - 64] = b1b[threadIdx.x - 64];
    if (threadIdx.x < 176) s_wa2[threadIdx.x] = w2a[threadIdx.x];
    __syncthreads();

    const int s = threadIdx.x & 3;
    const int pl = threadIdx.x >> 2;
    const int i = g_perm[blockIdx.x * 64 + pl] & NM_;   // orig index, sorted order

    const float4 pp = *reinterpret_cast<const float4*>(g_pos4 + i * 4);
    const int* np = g_nbr + (size_t)i * K_;

    float m[8];
#pragma unroll
    for (int q = 0; q < 8; q++) m[q] = -1e30f;

    const int kbeg = s * 16;
    bool active = true;
#pragma unroll 8
    for (int kk = 0; kk < 16; kk++) {
        int k = kbeg + kk;
        int j = __ldg(np + k) & NM_;
        if (k > 0 && j == i) active = false;
        if (active) fmax8(m, __ldg(g_t1h + j));
    }
#pragma unroll
    for (int off = 1; off < 4; off <<= 1)
#pragma unroll
        for (int q = 0; q < 8; q++)
            m[q] = fmaxf(m[q], __shfl_xor_sync(0xffffffffu, m[q], off));

    float a[8];
#pragma unroll
    for (int q = 0; q < 8; q++) {
        float v = pp.x * s_wad[q] + pp.y * s_wad[8 + q] + pp.z * s_wad[16 + q];
        a[q] = celu1(m[q] - v + s_ba[q]);
    }

    float y[8];
#pragma unroll
    for (int q = 0; q < 8; q++) y[q] = s_bb[q];
#pragma unroll
    for (int in = 0; in < 8; in++)
#pragma unroll
        for (int q = 0; q < 8; q++) y[q] = fmaf(a[in], s_wb[in * 8 + q], y[q]);
#pragma unroll
    for (int q = 0; q < 8; q++) y[q] = celu1(y[q]);

    const int oc = s * 4;
    float acc[4] = {0.f, 0.f, 0.f, 0.f};
#pragma unroll
    for (int in = 0; in < 8; in++)
#pragma unroll
        for (int q = 0; q < 4; q++) acc[q] = fmaf(y[in], s_wa2[in * 16 + oc + q], acc[q]);
    float pv[3] = {pp.x, pp.y, pp.z};
#pragma unroll
    for (int d = 0; d < 3; d++)
#pragma unroll
        for (int q = 0; q < 4; q++) acc[q] = fmaf(pv[d], s_wa2[(8 + d) * 16 + oc + q], acc[q]);

    reinterpret_cast<uint2*>(g_t2h)[i * 4 + s] = pack4(acc);   // write at orig index
}

// ---------------- Layer 2: t2(F=16) -> t3(FN=32); 4 threads/point ----------------
__global__ void __launch_bounds__(256)
layer2_kernel(const float* __restrict__ w2a, const float* __restrict__ b2a,
              const float* __restrict__ w2b, const float* __restrict__ b2b,
              const float* __restrict__ w3a)
{
    __shared__ float s_wb[256];
    __shared__ float s_wa2[19 * 32];
    __shared__ __align__(16) float s_a[64 * 17];

    if (threadIdx.x < 256) s_wb[threadIdx.x] = w2b[threadIdx.x];
    for (int k = threadIdx.x; k < 19 * 32; k += 256) s_wa2[k] = w3a[k];
    __syncthreads();

    const int s = threadIdx.x & 3;
    const int pl = threadIdx.x >> 2;
    const int i = g_perm[blockIdx.x * 64 + pl] & NM_;
    const int c = s & 1;
    const int h = s >> 1;

    const float4 pp = *reinterpret_cast<const float4*>(g_pos4 + i * 4);
    const int* np = g_nbr + (size_t)i * K_;
    const float* wa_d = w2a + 8 * 16;
    float* row = s_a + pl * 17;

    float m[8];
#pragma unroll
    for (int q = 0; q < 8; q++) m[q] = -1e30f;

    const int kbeg = h * 32;
    bool active = true;
#pragma unroll 8
    for (int kk = 0; kk < 32; kk++) {
        int k = kbeg + kk;
        int j = __ldg(np + k) & NM_;
        if (k > 0 && j == i) active = false;
        if (active) fmax8(m, __ldg(g_t2h + j * 2 + c));
    }
#pragma unroll
    for (int q = 0; q < 8; q++)
        m[q] = fmaxf(m[q], __shfl_xor_sync(0xffffffffu, m[q], 2));

#pragma unroll
    for (int q = 0; q < 8; q++) row[c * 8 + q] = m[q];
    __syncwarp();

    const int col = s * 4;
    float a[4];
#pragma unroll
    for (int q = 0; q < 4; q++) {
        float mm = row[col + q];
        float v = pp.x * wa_d[col + q] + pp.y * wa_d[16 + col + q] + pp.z * wa_d[32 + col + q];
        a[q] = celu1(mm - v + b2a[col + q]);
    }
#pragma unroll
    for (int q = 0; q < 4; q++) row[col + q] = a[q];
    __syncwarp();

    float y[4];
#pragma unroll
    for (int q = 0; q < 4; q++) y[q] = b2b[col + q];
#pragma unroll
    for (int in = 0; in < 16; in++) {
        float av = row[in];
#pragma unroll
        for (int q = 0; q < 4; q++) y[q] = fmaf(av, s_wb[in * 16 + col + q], y[q]);
    }
#pragma unroll
    for (int q = 0; q < 4; q++) y[q] = celu1(y[q]);
    __syncwarp();
#pragma unroll
    for (int q = 0; q < 4; q++) row[col + q] = y[q];
    __syncwarp();

    const int oc = s * 8;
    float acc[8];
#pragma unroll
    for (int q = 0; q < 8; q++) acc[q] = 0.0f;
#pragma unroll
    for (int in = 0; in < 16; in++) {
        float yv = row[in];
#pragma unroll
        for (int q = 0; q < 8; q++) acc[q] = fmaf(yv, s_wa2[in * 32 + oc + q], acc[q]);
    }
    float pv[3] = {pp.x, pp.y, pp.z};
#pragma unroll
    for (int d = 0; d < 3; d++)
#pragma unroll
        for (int q = 0; q < 8; q++) acc[q] = fmaf(pv[d], s_wa2[(16 + d) * 32 + oc + q], acc[q]);

    g_t3h[i * 4 + s] = pack8(acc);
}

// ---------------- Layer 3: t3(F=32) -> out(fp32); 8 threads/point ----------------
__global__ void __launch_bounds__(256)
layer3_kernel(const float* __restrict__ w3a, const float* __restrict__ b3a,
              const float* __restrict__ w3b, const float* __restrict__ b3b,
              float* __restrict__ out_feat)
{
    __shared__ float s_wb[1024];
    __shared__ __align__(16) float s_a[32 * 33];

    for (int k = threadIdx.x; k < 1024; k += 256) s_wb[k] = w3b[k];
    __syncthreads();

    const int s = threadIdx.x & 7;
    const int pl = threadIdx.x >> 3;
    const int i = g_perm[blockIdx.x * 32 + pl] & NM_;
    const int c = s & 3;
    const int h = s >> 2;

    const float4 pp = *reinterpret_cast<const float4*>(g_pos4 + i * 4);
    const int* np = g_nbr + (size_t)i * K_;
    const float* wa_d = w3a + 16 * 32;
    float* row = s_a + pl * 33;

    float m[8];
#pragma unroll
    for (int q = 0; q < 8; q++) m[q] = -1e30f;

    const int kbeg = h * 32;
    bool active = true;
#pragma unroll 8
    for (int kk = 0; kk < 32; kk++) {
        int k = kbeg + kk;
        int j = __ldg(np + k) & NM_;
        if (k > 0 && j == i) active = false;
        if (active) fmax8(m, __ldg(g_t3h + j * 4 + c));
    }
#pragma unroll
    for (int q = 0; q < 8; q++)
        m[q] = fmaxf(m[q], __shfl_xor_sync(0xffffffffu, m[q], 4));

#pragma unroll
    for (int q = 0; q < 8; q++) row[c * 8 + q] = m[q];
    __syncwarp();

    const int col = s * 4;
    float a[4];
#pragma unroll
    for (int q = 0; q < 4; q++) {
        float mm = row[col + q];
        float v = pp.x * wa_d[col + q] + pp.y * wa_d[32 + col + q] + pp.z * wa_d[64 + col + q];
        a[q] = celu1(mm - v + b3a[col + q]);
    }
#pragma unroll
    for (int q = 0; q < 4; q++) row[col + q] = a[q];
    __syncwarp();

    float y[4];
#pragma unroll
    for (int q = 0; q < 4; q++) y[q] = b3b[col + q];
#pragma unroll
    for (int in = 0; in < 32; in++) {
        float av = row[in];
#pragma unroll
        for (int q = 0; q < 4; q++) y[q] = fmaf(av, s_wb[in * 32 + col + q], y[q]);
    }
#pragma unroll
    for (int q = 0; q < 4; q++) y[q] = celu1(y[q]);

    *reinterpret_cast<float4*>(out_feat + (size_t)i * 32 + col) =
        make_float4(y[0], y[1], y[2], y[3]);
}

extern "C" void kernel_launch(void* const* d_in, const int* in_sizes, int n_in,
                              void* d_out, int out_size)
{
    const float* pos = (const float*)d_in[0];
    const void* in_index = d_in[4];
    const float* w1a = (const float*)d_in[5];
    const float* b1a = (const float*)d_in[6];
    const float* w1b = (const float*)d_in[7];
    const float* b1b = (const float*)d_in[8];
    const float* w2a = (const float*)d_in[9];
    const float* b2a = (const float*)d_in[10];
    const float* w2b = (const float*)d_in[11];
    const float* b2b = (const float*)d_in[12];
    const float* w3a = (const float*)d_in[13];
    const float* b3a = (const float*)d_in[14];
    const float* w3b = (const float*)d_in[15];
    const float* b3b = (const float*)d_in[16];
    float* out = (float*)d_out;

    detect_kernel<<<1, 256>>>(in_index);
    prep_kernel<<<2048, 256>>>(pos, in_index, w1a, out, out_size);
    scan_kernel<<<1, 32>>>();
    scatter_kernel<<<512, 256>>>();

    layer1_kernel<<<N_ / 64, 256>>>(w1a, b1a, w1b, b1b, w2a);
    layer2_kernel<<<N_ / 64, 256>>>(w2a, b2a, w2b, b2b, w3a);
    layer3_kernel<<<N_ / 32, 256>>>(w3a, b3a, w3b, b3b, out + 3 * N_);
}

// round 15
// speedup vs baseline: 1.0151x; 1.0149x over previous
#include <cuda_runtime.h>
#include <cuda_fp16.h>
#include <math.h>

constexpr int N_ = 65536;
constexpr int K_ = 64;
constexpr int G_ = 16;
constexpr int NC_ = G_ * G_ * G_;
constexpr unsigned NM_ = N_ - 1;    // power-of-two mask

// ---------------- device scratch ----------------
__device__ uint4 g_t1h[N_];          // fp16 rows: 8 halves  = 16B (orig index space)
__device__ uint4 g_t2h[N_ * 2];      // fp16 rows: 16 halves = 32B
__device__ uint4 g_t3h[N_ * 4];      // fp16 rows: 32 halves = 64B
__device__ __align__(16) float g_pos4[N_ * 4];
__device__ int g_nbr[N_ * K_];
__device__ int g_perm[N_];           // processing order: sorted slot -> orig index
__device__ unsigned short g_cid[N_];
__device__ int g_hist[NC_];
__device__ int g_cursor[NC_];
__device__ int g_idx_is64;

__device__ __forceinline__ float celu1(float x) {
    return x > 0.0f ? x : expm1f(x);
}

__device__ __forceinline__ void fmax8(float* m, uint4 u) {
    __half2* h = (__half2*)&u;
#pragma unroll
    for (int q = 0; q < 4; q++) {
        float2 f = __half22float2(h[q]);
        m[2 * q]     = fmaxf(m[2 * q], f.x);
        m[2 * q + 1] = fmaxf(m[2 * q + 1], f.y);
    }
}

__device__ __forceinline__ uint4 pack8(const float* v) {
    uint4 u;
    __half2* h = (__half2*)&u;
#pragma unroll
    for (int q = 0; q < 4; q++)
        h[q] = __floats2half2_rn(v[2 * q], v[2 * q + 1]);
    return u;
}

__device__ __forceinline__ uint2 pack4(const float* v) {
    uint2 u;
    __half2* h = (__half2*)&u;
    h[0] = __floats2half2_rn(v[0], v[1]);
    h[1] = __floats2half2_rn(v[2], v[3]);
    return u;
}

// ---------------- K0: dtype detect + zero hist ----------------
__global__ void detect_kernel(const void* __restrict__ idx_raw)
{
    for (int c = threadIdx.x; c < NC_; c += blockDim.x) g_hist[c] = 0;
    if (threadIdx.x == 0) {
        const long long* p = (const long long*)idx_raw;
        const long long mid = 1 << 20;
        int ok = 1;
        for (int t = 0; t < 32; t++) {
            long long v = p[mid + t];
            if (v < 0 || v >= N_) { ok = 0; break; }
        }
        g_idx_is64 = ok;
    }
}

// ---------------- K1: prep — idx convert, pos4, t1, cell hist, out pos copy ----------------
__global__ void prep_kernel(const float* __restrict__ pos,
                            const void* __restrict__ idx_raw,
                            const float* __restrict__ w1a,
                            float* __restrict__ out, int out_size)
{
    const int stride = gridDim.x * blockDim.x;
    const int tid = blockIdx.x * blockDim.x + threadIdx.x;

    if (g_idx_is64) {
        const long long* p = (const long long*)idx_raw;
        for (int e = tid; e < N_ * K_; e += stride)
            g_nbr[e] = ((int)p[e]) & NM_;
    } else {
        const int* p = (const int*)idx_raw;
        for (int e = tid; e < N_ * K_; e += stride)
            g_nbr[e] = p[e] & NM_;
    }

    for (int i = tid; i < N_; i += stride) {
        float p0 = pos[i * 3 + 0], p1 = pos[i * 3 + 1], p2 = pos[i * 3 + 2];
        *reinterpret_cast<float4*>(g_pos4 + i * 4) = make_float4(p0, p1, p2, 0.0f);
        float t[8];
#pragma unroll
        for (int c = 0; c < 8; c++) {
            t[c] = p0 * (w1a[0 * 8 + c] + w1a[3 * 8 + c])
                 + p1 * (w1a[1 * 8 + c] + w1a[4 * 8 + c])
                 + p2 * (w1a[2 * 8 + c] + w1a[5 * 8 + c]);
        }
        g_t1h[i] = pack8(t);

        int cx = min(G_ - 1, max(0, (int)(p0 * 16.0f)));
        int cy = min(G_ - 1, max(0, (int)(p1 * 16.0f)));
        int cz = min(G_ - 1, max(0, (int)(p2 * 16.0f)));
        int cid = (cx * G_ + cy) * G_ + cz;
        g_cid[i] = (unsigned short)cid;
        atomicAdd(&g_hist[cid], 1);
    }

    for (int e = tid; e < 3 * N_; e += stride) out[e] = pos[e];
    for (int e = 35 * N_ + tid; e < out_size; e += stride) out[e] = 0.0f;
}

// ---------------- K2: exclusive scan of 4096 counts, single warp ----------------
__global__ void scan_kernel()
{
    const int lane = threadIdx.x;
    const int base = lane * (NC_ / 32);
    int s = 0;
    for (int c = 0; c < NC_ / 32; c++) s += g_hist[base + c];
    int incl = s;
#pragma unroll
    for (int off = 1; off < 32; off <<= 1) {
        int x = __shfl_up_sync(0xffffffffu, incl, off);
        if (lane >= off) incl += x;
    }
    int run = incl - s;
    for (int c = 0; c < NC_ / 32; c++) {
        g_cursor[base + c] = run;
        run += g_hist[base + c];
    }
}

// ---------------- K3: scatter — build processing order ----------------
__global__ void scatter_kernel()
{
    const int stride = gridDim.x * blockDim.x;
    const int tid = blockIdx.x * blockDim.x + threadIdx.x;
    for (int i = tid; i < N_; i += stride) {
        int s = atomicAdd(&g_cursor[g_cid[i]], 1) & NM_;
        g_perm[s] = i;
    }
}

// ---------------- Layer 1: t1(F=8) -> t2(FN=16); 4 threads/point, sorted processing order ----------------
__global__ void __launch_bounds__(256)
layer1_kernel(const float* __restrict__ w1a, const float* __restrict__ b1a,
              const float* __restrict__ w1b, const float* __restrict__ b1b,
              const float* __restrict__ w2a)
{
    __shared__ float s_wad[24];
    __shared__ float s_ba[8];
    __shared__ float s_wb[64];
    __shared__ float s_bb[8];
    __shared__ float s_wa2[11 * 16];

    if (threadIdx.x < 24) s_wad[threadIdx.x] = w1a[24 + threadIdx.x];
    if (threadIdx.x < 8)  s_ba[threadIdx.x] = b1a[threadIdx.x];
    if (threadIdx.x < 64) s_wb[threadIdx.x] = w1b[threadIdx.x];
    if (threadIdx.x >= 64 && threadIdx.x < 72) s_bb[threadIdx.x - 64] = b1b[threadIdx.x - 64];
    if (threadIdx.x < 176) s_wa2[threadIdx.x] = w2a[threadIdx.x];
    __syncthreads();

    const int s = threadIdx.x & 3;
    const int pl = threadIdx.x >> 2;
    const int i = g_perm[blockIdx.x * 64 + pl] & NM_;   // orig index, sorted order

    const float4 pp = *reinterpret_cast<const float4*>(g_pos4 + i * 4);
    const int* np = g_nbr + (size_t)i * K_;

    float m[8];
#pragma unroll
    for (int q = 0; q < 8; q++) m[q] = -1e30f;

    const int kbeg = s * 16;
    bool active = true;
#pragma unroll 8
    for (int kk = 0; kk < 16; kk++) {
        int k = kbeg + kk;
        int j = __ldg(np + k) & NM_;
        if (k > 0 && j == i) active = false;
        if (active) fmax8(m, __ldg(g_t1h + j));
    }
#pragma unroll
    for (int off = 1; off < 4; off <<= 1)
#pragma unroll
        for (int q = 0; q < 8; q++)
            m[q] = fmaxf(m[q], __shfl_xor_sync(0xffffffffu, m[q], off));

    float a[8];
#pragma unroll
    for (int q = 0; q < 8; q++) {
        float v = pp.x * s_wad[q] + pp.y * s_wad[8 + q] + pp.z * s_wad[16 + q];
        a[q] = celu1(m[q] - v + s_ba[q]);
    }

    float y[8];
#pragma unroll
    for (int q = 0; q < 8; q++) y[q] = s_bb[q];
#pragma unroll
    for (int in = 0; in < 8; in++)
#pragma unroll
        for (int q = 0; q < 8; q++) y[q] = fmaf(a[in], s_wb[in * 8 + q], y[q]);
#pragma unroll
    for (int q = 0; q < 8; q++) y[q] = celu1(y[q]);

    const int oc = s * 4;
    float acc[4] = {0.f, 0.f, 0.f, 0.f};
#pragma unroll
    for (int in = 0; in < 8; in++)
#pragma unroll
        for (int q = 0; q < 4; q++) acc[q] = fmaf(y[in], s_wa2[in * 16 + oc + q], acc[q]);
    float pv[3] = {pp.x, pp.y, pp.z};
#pragma unroll
    for (int d = 0; d < 3; d++)
#pragma unroll
        for (int q = 0; q < 4; q++) acc[q] = fmaf(pv[d], s_wa2[(8 + d) * 16 + oc + q], acc[q]);

    reinterpret_cast<uint2*>(g_t2h)[i * 4 + s] = pack4(acc);   // write at orig index
}

// ---------------- Layer 2: t2(F=16) -> t3(FN=32); 4 threads/point ----------------
__global__ void __launch_bounds__(256)
layer2_kernel(const float* __restrict__ w2a, const float* __restrict__ b2a,
              const float* __restrict__ w2b, const float* __restrict__ b2b,
              const float* __restrict__ w3a)
{
    __shared__ float s_wb[256];
    __shared__ float s_wa2[19 * 32];
    __shared__ __align__(16) float s_a[64 * 17];

    if (threadIdx.x < 256) s_wb[threadIdx.x] = w2b[threadIdx.x];
    for (int k = threadIdx.x; k < 19 * 32; k += 256) s_wa2[k] = w3a[k];
    __syncthreads();

    const int s = threadIdx.x & 3;
    const int pl = threadIdx.x >> 2;
    const int i = g_perm[blockIdx.x * 64 + pl] & NM_;
    const int c = s & 1;
    const int h = s >> 1;

    const float4 pp = *reinterpret_cast<const float4*>(g_pos4 + i * 4);
    const int* np = g_nbr + (size_t)i * K_;
    const float* wa_d = w2a + 8 * 16;
    float* row = s_a + pl * 17;

    float m[8];
#pragma unroll
    for (int q = 0; q < 8; q++) m[q] = -1e30f;

    const int kbeg = h * 32;
    bool active = true;
#pragma unroll 8
    for (int kk = 0; kk < 32; kk++) {
        int k = kbeg + kk;
        int j = __ldg(np + k) & NM_;
        if (k > 0 && j == i) active = false;
        if (active) fmax8(m, __ldg(g_t2h + j * 2 + c));
    }
#pragma unroll
    for (int q = 0; q < 8; q++)
        m[q] = fmaxf(m[q], __shfl_xor_sync(0xffffffffu, m[q], 2));

#pragma unroll
    for (int q = 0; q < 8; q++) row[c * 8 + q] = m[q];
    __syncwarp();

    const int col = s * 4;
    float a[4];
#pragma unroll
    for (int q = 0; q < 4; q++) {
        float mm = row[col + q];
        float v = pp.x * wa_d[col + q] + pp.y * wa_d[16 + col + q] + pp.z * wa_d[32 + col + q];
        a[q] = celu1(mm - v + b2a[col + q]);
    }
#pragma unroll
    for (int q = 0; q < 4; q++) row[col + q] = a[q];
    __syncwarp();

    float y[4];
#pragma unroll
    for (int q = 0; q < 4; q++) y[q] = b2b[col + q];
#pragma unroll
    for (int in = 0; in < 16; in++) {
        float av = row[in];
#pragma unroll
        for (int q = 0; q < 4; q++) y[q] = fmaf(av, s_wb[in * 16 + col + q], y[q]);
    }
#pragma unroll
    for (int q = 0; q < 4; q++) y[q] = celu1(y[q]);
    __syncwarp();
#pragma unroll
    for (int q = 0; q < 4; q++) row[col + q] = y[q];
    __syncwarp();

    const int oc = s * 8;
    float acc[8];
#pragma unroll
    for (int q = 0; q < 8; q++) acc[q] = 0.0f;
#pragma unroll
    for (int in = 0; in < 16; in++) {
        float yv = row[in];
#pragma unroll
        for (int q = 0; q < 8; q++) acc[q] = fmaf(yv, s_wa2[in * 32 + oc + q], acc[q]);
    }
    float pv[3] = {pp.x, pp.y, pp.z};
#pragma unroll
    for (int d = 0; d < 3; d++)
#pragma unroll
        for (int q = 0; q < 8; q++) acc[q] = fmaf(pv[d], s_wa2[(16 + d) * 32 + oc + q], acc[q]);

    g_t3h[i * 4 + s] = pack8(acc);
}

// ---------------- Layer 3: t3(F=32) -> out(fp32); 8 threads/point ----------------
__global__ void __launch_bounds__(256)
layer3_kernel(const float* __restrict__ w3a, const float* __restrict__ b3a,
              const float* __restrict__ w3b, const float* __restrict__ b3b,
              float* __restrict__ out_feat)
{
    __shared__ float s_wb[1024];
    __shared__ __align__(16) float s_a[32 * 33];

    for (int k = threadIdx.x; k < 1024; k += 256) s_wb[k] = w3b[k];
    __syncthreads();

    const int s = threadIdx.x & 7;
    const int pl = threadIdx.x >> 3;
    const int i = g_perm[blockIdx.x * 32 + pl] & NM_;
    const int c = s & 3;
    const int h = s >> 2;

    const float4 pp = *reinterpret_cast<const float4*>(g_pos4 + i * 4);
    const int* np = g_nbr + (size_t)i * K_;
    const float* wa_d = w3a + 16 * 32;
    float* row = s_a + pl * 33;

    float m[8];
#pragma unroll
    for (int q = 0; q < 8; q++) m[q] = -1e30f;

    const int kbeg = h * 32;
    bool active = true;
#pragma unroll 8
    for (int kk = 0; kk < 32; kk++) {
        int k = kbeg + kk;
        int j = __ldg(np + k) & NM_;
        if (k > 0 && j == i) active = false;
        if (active) fmax8(m, __ldg(g_t3h + j * 4 + c));
    }
#pragma unroll
    for (int q = 0; q < 8; q++)
        m[q] = fmaxf(m[q], __shfl_xor_sync(0xffffffffu, m[q], 4));

#pragma unroll
    for (int q = 0; q < 8; q++) row[c * 8 + q] = m[q];
    __syncwarp();

    const int col = s * 4;
    float a[4];
#pragma unroll
    for (int q = 0; q < 4; q++) {
        float mm = row[col + q];
        float v = pp.x * wa_d[col + q] + pp.y * wa_d[32 + col + q] + pp.z * wa_d[64 + col + q];
        a[q] = celu1(mm - v + b3a[col + q]);
    }
#pragma unroll
    for (int q = 0; q < 4; q++) row[col + q] = a[q];
    __syncwarp();

    float y[4];
#pragma unroll
    for (int q = 0; q < 4; q++) y[q] = b3b[col + q];
#pragma unroll
    for (int in = 0; in < 32; in++) {
        float av = row[in];
#pragma unroll
        for (int q = 0; q < 4; q++) y[q] = fmaf(av, s_wb[in * 32 + col + q], y[q]);
    }
#pragma unroll
    for (int q = 0; q < 4; q++) y[q] = celu1(y[q]);

    *reinterpret_cast<float4*>(out_feat + (size_t)i * 32 + col) =
        make_float4(y[0], y[1], y[2], y[3]);
}

extern "C" void kernel_launch(void* const* d_in, const int* in_sizes, int n_in,
                              void* d_out, int out_size)
{
    const float* pos = (const float*)d_in[0];
    const void* in_index = d_in[4];
    const float* w1a = (const float*)d_in[5];
    const float* b1a = (const float*)d_in[6];
    const float* w1b = (const float*)d_in[7];
    const float* b1b = (const float*)d_in[8];
    const float* w2a = (const float*)d_in[9];
    const float* b2a = (const float*)d_in[10];
    const float* w2b = (const float*)d_in[11];
    const float* b2b = (const float*)d_in[12];
    const float* w3a = (const float*)d_in[13];
    const float* b3a = (const float*)d_in[14];
    const float* w3b = (const float*)d_in[15];
    const float* b3b = (const float*)d_in[16];
    float* out = (float*)d_out;

    detect_kernel<<<1, 256>>>(in_index);
    prep_kernel<<<2048, 256>>>(pos, in_index, w1a, out, out_size);
    scan_kernel<<<1, 32>>>();
    scatter_kernel<<<512, 256>>>();

    layer1_kernel<<<N_ / 64, 256>>>(w1a, b1a, w1b, b1b, w2a);
    layer2_kernel<<<N_ / 64, 256>>>(w2a, b2a, w2b, b2b, w3a);
    layer3_kernel<<<N_ / 32, 256>>>(w3a, b3a, w3b, b3b, out + 3 * N_);
}

// round 16
// speedup vs baseline: 1.4172x; 1.3961x over previous
#include <cuda_runtime.h>
#include <cuda_fp16.h>
#include <math.h>

constexpr int N_ = 65536;
constexpr int K_ = 64;
constexpr unsigned NM_ = N_ - 1;    // power-of-two mask

// ---------------- device scratch ----------------
__device__ uint4 g_t1h[N_];          // fp16 rows: 8 halves  = 16B
__device__ uint4 g_t2h[N_ * 2];      // fp16 rows: 16 halves = 32B
__device__ uint4 g_t3h[N_ * 4];      // fp16 rows: 32 halves = 64B
__device__ __align__(16) float g_pos4[N_ * 4];
__device__ int g_nbrT[K_ * N_];      // TRANSPOSED: nbrT[k*N + i]
__device__ int g_idx_is64;

__device__ __forceinline__ float celu1(float x) {
    return x > 0.0f ? x : expm1f(x);
}

__device__ __forceinline__ void fmax8(float* m, uint4 u) {
    __half2* h = (__half2*)&u;
#pragma unroll
    for (int q = 0; q < 4; q++) {
        float2 f = __half22float2(h[q]);
        m[2 * q]     = fmaxf(m[2 * q], f.x);
        m[2 * q + 1] = fmaxf(m[2 * q + 1], f.y);
    }
}

__device__ __forceinline__ uint4 pack8(const float* v) {
    uint4 u;
    __half2* h = (__half2*)&u;
#pragma unroll
    for (int q = 0; q < 4; q++)
        h[q] = __floats2half2_rn(v[2 * q], v[2 * q + 1]);
    return u;
}

__device__ __forceinline__ uint2 pack4(const float* v) {
    uint2 u;
    __half2* h = (__half2*)&u;
    h[0] = __floats2half2_rn(v[0], v[1]);
    h[1] = __floats2half2_rn(v[2], v[3]);
    return u;
}

// ---------------- K0: dtype detect ----------------
__global__ void detect_kernel(const void* __restrict__ idx_raw)
{
    if (threadIdx.x == 0) {
        const long long* p = (const long long*)idx_raw;
        const long long mid = 1 << 20;
        int ok = 1;
        for (int t = 0; t < 32; t++) {
            long long v = p[mid + t];
            if (v < 0 || v >= N_) { ok = 0; break; }
        }
        g_idx_is64 = ok;
    }
}

// ---------------- K1: transpose neighbor lists to k-major ----------------
// one block per 64-point tile; smem 64x64 int tile
__global__ void __launch_bounds__(256)
transpose_kernel(const void* __restrict__ idx_raw)
{
    __shared__ int tile[64][65];
    const int tbase = blockIdx.x * 64;            // point base
    const int col = threadIdx.x & 63;             // 0..63
    const int roff = threadIdx.x >> 6;            // 0..3

    if (g_idx_is64) {
        const long long* p = (const long long*)idx_raw;
#pragma unroll
        for (int r = 0; r < 64; r += 4) {
            int row = r + roff;                   // point within tile
            tile[row][col] = ((int)p[(size_t)(tbase + row) * K_ + col]) & NM_;
        }
    } else {
        const int* p = (const int*)idx_raw;
#pragma unroll
        for (int r = 0; r < 64; r += 4) {
            int row = r + roff;
            tile[row][col] = p[(size_t)(tbase + row) * K_ + col] & NM_;
        }
    }
    __syncthreads();

#pragma unroll
    for (int kb = 0; kb < 64; kb += 4) {
        int k = kb + roff;
        g_nbrT[(size_t)k * N_ + tbase + col] = tile[col][k];
    }
}

// ---------------- K2: prep — pos4, t1, out pos copy, tail zero ----------------
__global__ void prep_kernel(const float* __restrict__ pos,
                            const float* __restrict__ w1a,
                            float* __restrict__ out, int out_size)
{
    const int stride = gridDim.x * blockDim.x;
    const int tid = blockIdx.x * blockDim.x + threadIdx.x;

    for (int i = tid; i < N_; i += stride) {
        float p0 = pos[i * 3 + 0], p1 = pos[i * 3 + 1], p2 = pos[i * 3 + 2];
        *reinterpret_cast<float4*>(g_pos4 + i * 4) = make_float4(p0, p1, p2, 0.0f);
        float t[8];
#pragma unroll
        for (int c = 0; c < 8; c++) {
            t[c] = p0 * (w1a[0 * 8 + c] + w1a[3 * 8 + c])
                 + p1 * (w1a[1 * 8 + c] + w1a[4 * 8 + c])
                 + p2 * (w1a[2 * 8 + c] + w1a[5 * 8 + c]);
        }
        g_t1h[i] = pack8(t);
    }

    for (int e = tid; e < 3 * N_; e += stride) out[e] = pos[e];
    for (int e = 35 * N_ + tid; e < out_size; e += stride) out[e] = 0.0f;
}

// ---------------- Layer 1: t1(F=8) -> t2(FN=16); 4 threads/point (K-split x4) ----------------
__global__ void __launch_bounds__(256)
layer1_kernel(const float* __restrict__ w1a, const float* __restrict__ b1a,
              const float* __restrict__ w1b, const float* __restrict__ b1b,
              const float* __restrict__ w2a)
{
    __shared__ float s_wad[24];
    __shared__ float s_ba[8];
    __shared__ float s_wb[64];
    __shared__ float s_bb[8];
    __shared__ float s_wa2[11 * 16];

    if (threadIdx.x < 24) s_wad[threadIdx.x] = w1a[24 + threadIdx.x];
    if (threadIdx.x < 8)  s_ba[threadIdx.x] = b1a[threadIdx.x];
    if (threadIdx.x < 64) s_wb[threadIdx.x] = w1b[threadIdx.x];
    if (threadIdx.x >= 64 && threadIdx.x < 72) s_bb[threadIdx.x - 64] = b1b[threadIdx.x - 64];
    if (threadIdx.x < 176) s_wa2[threadIdx.x] = w2a[threadIdx.x];
    __syncthreads();

    const int s = threadIdx.x & 3;
    const int pl = threadIdx.x >> 2;
    const int i = blockIdx.x * 64 + pl;

    const float4 pp = *reinterpret_cast<const float4*>(g_pos4 + i * 4);

    float m[8];
#pragma unroll
    for (int q = 0; q < 8; q++) m[q] = -1e30f;

    const int kbeg = s * 16;
    bool active = true;
#pragma unroll 8
    for (int kk = 0; kk < 16; kk++) {
        int k = kbeg + kk;
        int j = __ldg(g_nbrT + (size_t)k * N_ + i) & NM_;
        if (k > 0 && j == i) active = false;
        if (active) fmax8(m, __ldg(g_t1h + j));
    }
#pragma unroll
    for (int off = 1; off < 4; off <<= 1)
#pragma unroll
        for (int q = 0; q < 8; q++)
            m[q] = fmaxf(m[q], __shfl_xor_sync(0xffffffffu, m[q], off));

    float a[8];
#pragma unroll
    for (int q = 0; q < 8; q++) {
        float v = pp.x * s_wad[q] + pp.y * s_wad[8 + q] + pp.z * s_wad[16 + q];
        a[q] = celu1(m[q] - v + s_ba[q]);
    }

    float y[8];
#pragma unroll
    for (int q = 0; q < 8; q++) y[q] = s_bb[q];
#pragma unroll
    for (int in = 0; in < 8; in++)
#pragma unroll
        for (int q = 0; q < 8; q++) y[q] = fmaf(a[in], s_wb[in * 8 + q], y[q]);
#pragma unroll
    for (int q = 0; q < 8; q++) y[q] = celu1(y[q]);

    const int oc = s * 4;
    float acc[4] = {0.f, 0.f, 0.f, 0.f};
#pragma unroll
    for (int in = 0; in < 8; in++)
#pragma unroll
        for (int q = 0; q < 4; q++) acc[q] = fmaf(y[in], s_wa2[in * 16 + oc + q], acc[q]);
    float pv[3] = {pp.x, pp.y, pp.z};
#pragma unroll
    for (int d = 0; d < 3; d++)
#pragma unroll
        for (int q = 0; q < 4; q++) acc[q] = fmaf(pv[d], s_wa2[(8 + d) * 16 + oc + q], acc[q]);

    reinterpret_cast<uint2*>(g_t2h)[i * 4 + s] = pack4(acc);
}

// ---------------- Layer 2: t2(F=16) -> t3(FN=32); 4 threads/point ----------------
__global__ void __launch_bounds__(256)
layer2_kernel(const float* __restrict__ w2a, const float* __restrict__ b2a,
              const float* __restrict__ w2b, const float* __restrict__ b2b,
              const float* __restrict__ w3a)
{
    __shared__ float s_wb[256];
    __shared__ float s_wa2[19 * 32];
    __shared__ __align__(16) float s_a[64 * 17];

    if (threadIdx.x < 256) s_wb[threadIdx.x] = w2b[threadIdx.x];
    for (int k = threadIdx.x; k < 19 * 32; k += 256) s_wa2[k] = w3a[k];
    __syncthreads();

    const int s = threadIdx.x & 3;
    const int pl = threadIdx.x >> 2;
    const int i = blockIdx.x * 64 + pl;
    const int c = s & 1;
    const int h = s >> 1;

    const float4 pp = *reinterpret_cast<const float4*>(g_pos4 + i * 4);
    const float* wa_d = w2a + 8 * 16;
    float* row = s_a + pl * 17;

    float m[8];
#pragma unroll
    for (int q = 0; q < 8; q++) m[q] = -1e30f;

    const int kbeg = h * 32;
    bool active = true;
#pragma unroll 8
    for (int kk = 0; kk < 32; kk++) {
        int k = kbeg + kk;
        int j = __ldg(g_nbrT + (size_t)k * N_ + i) & NM_;
        if (k > 0 && j == i) active = false;
        if (active) fmax8(m, __ldg(g_t2h + j * 2 + c));
    }
#pragma unroll
    for (int q = 0; q < 8; q++)
        m[q] = fmaxf(m[q], __shfl_xor_sync(0xffffffffu, m[q], 2));

#pragma unroll
    for (int q = 0; q < 8; q++) row[c * 8 + q] = m[q];
    __syncwarp();

    const int col = s * 4;
    float a[4];
#pragma unroll
    for (int q = 0; q < 4; q++) {
        float mm = row[col + q];
        float v = pp.x * wa_d[col + q] + pp.y * wa_d[16 + col + q] + pp.z * wa_d[32 + col + q];
        a[q] = celu1(mm - v + b2a[col + q]);
    }
#pragma unroll
    for (int q = 0; q < 4; q++) row[col + q] = a[q];
    __syncwarp();

    float y[4];
#pragma unroll
    for (int q = 0; q < 4; q++) y[q] = b2b[col + q];
#pragma unroll
    for (int in = 0; in < 16; in++) {
        float av = row[in];
#pragma unroll
        for (int q = 0; q < 4; q++) y[q] = fmaf(av, s_wb[in * 16 + col + q], y[q]);
    }
#pragma unroll
    for (int q = 0; q < 4; q++) y[q] = celu1(y[q]);
    __syncwarp();
#pragma unroll
    for (int q = 0; q < 4; q++) row[col + q] = y[q];
    __syncwarp();

    const int oc = s * 8;
    float acc[8];
#pragma unroll
    for (int q = 0; q < 8; q++) acc[q] = 0.0f;
#pragma unroll
    for (int in = 0; in < 16; in++) {
        float yv = row[in];
#pragma unroll
        for (int q = 0; q < 8; q++) acc[q] = fmaf(yv, s_wa2[in * 32 + oc + q], acc[q]);
    }
    float pv[3] = {pp.x, pp.y, pp.z};
#pragma unroll
    for (int d = 0; d < 3; d++)
#pragma unroll
        for (int q = 0; q < 8; q++) acc[q] = fmaf(pv[d], s_wa2[(16 + d) * 32 + oc + q], acc[q]);

    g_t3h[i * 4 + s] = pack8(acc);
}

// ---------------- Layer 3: t3(F=32) -> out(fp32); 8 threads/point ----------------
__global__ void __launch_bounds__(256)
layer3_kernel(const float* __restrict__ w3a, const float* __restrict__ b3a,
              const float* __restrict__ w3b, const float* __restrict__ b3b,
              float* __restrict__ out_feat)
{
    __shared__ float s_wb[1024];
    __shared__ __align__(16) float s_a[32 * 33];

    for (int k = threadIdx.x; k < 1024; k += 256) s_wb[k] = w3b[k];
    __syncthreads();

    const int s = threadIdx.x & 7;
    const int pl = threadIdx.x >> 3;
    const int i = blockIdx.x * 32 + pl;
    const int c = s & 3;
    const int h = s >> 2;

    const float4 pp = *reinterpret_cast<const float4*>(g_pos4 + i * 4);
    const float* wa_d = w3a + 16 * 32;
    float* row = s_a + pl * 33;

    float m[8];
#pragma unroll
    for (int q = 0; q < 8; q++) m[q] = -1e30f;

    const int kbeg = h * 32;
    bool active = true;
#pragma unroll 8
    for (int kk = 0; kk < 32; kk++) {
        int k = kbeg + kk;
        int j = __ldg(g_nbrT + (size_t)k * N_ + i) & NM_;
        if (k > 0 && j == i) active = false;
        if (active) fmax8(m, __ldg(g_t3h + j * 4 + c));
    }
#pragma unroll
    for (int q = 0; q < 8; q++)
        m[q] = fmaxf(m[q], __shfl_xor_sync(0xffffffffu, m[q], 4));

#pragma unroll
    for (int q = 0; q < 8; q++) row[c * 8 + q] = m[q];
    __syncwarp();

    const int col = s * 4;
    float a[4];
#pragma unroll
    for (int q = 0; q < 4; q++) {
        float mm = row[col + q];
        float v = pp.x * wa_d[col + q] + pp.y * wa_d[32 + col + q] + pp.z * wa_d[64 + col + q];
        a[q] = celu1(mm - v + b3a[col + q]);
    }
#pragma unroll
    for (int q = 0; q < 4; q++) row[col + q] = a[q];
    __syncwarp();

    float y[4];
#pragma unroll
    for (int q = 0; q < 4; q++) y[q] = b3b[col + q];
#pragma unroll
    for (int in = 0; in < 32; in++) {
        float av = row[in];
#pragma unroll
        for (int q = 0; q < 4; q++) y[q] = fmaf(av, s_wb[in * 32 + col + q], y[q]);
    }
#pragma unroll
    for (int q = 0; q < 4; q++) y[q] = celu1(y[q]);

    *reinterpret_cast<float4*>(out_feat + (size_t)i * 32 + col) =
        make_float4(y[0], y[1], y[2], y[3]);
}

extern "C" void kernel_launch(void* const* d_in, const int* in_sizes, int n_in,
                              void* d_out, int out_size)
{
    const float* pos = (const float*)d_in[0];
    const void* in_index = d_in[4];
    const float* w1a = (const float*)d_in[5];
    const float* b1a = (const float*)d_in[6];
    const float* w1b = (const float*)d_in[7];
    const float* b1b = (const float*)d_in[8];
    const float* w2a = (const float*)d_in[9];
    const float* b2a = (const float*)d_in[10];
    const float* w2b = (const float*)d_in[11];
    const float* b2b = (const float*)d_in[12];
    const float* w3a = (const float*)d_in[13];
    const float* b3a = (const float*)d_in[14];
    const float* w3b = (const float*)d_in[15];
    const float* b3b = (const float*)d_in[16];
    float* out = (float*)d_out;

    detect_kernel<<<1, 32>>>(in_index);
    transpose_kernel<<<N_ / 64, 256>>>(in_index);
    prep_kernel<<<1024, 256>>>(pos, w1a, out, out_size);

    layer1_kernel<<<N_ / 64, 256>>>(w1a, b1a, w1b, b1b, w2a);
    layer2_kernel<<<N_ / 64, 256>>>(w2a, b2a, w2b, b2b, w3a);
    layer3_kernel<<<N_ / 32, 256>>>(w3a, b3a, w3b, b3b, out + 3 * N_);
}

// round 17
// speedup vs baseline: 1.4299x; 1.0090x over previous
#include <cuda_runtime.h>
#include <cuda_fp16.h>
#include <math.h>

constexpr int N_ = 65536;
constexpr int K_ = 64;
constexpr unsigned NM_ = N_ - 1;    // power-of-two mask

// ---------------- device scratch ----------------
__device__ uint4 g_t1h[N_];          // fp16 rows: 8 halves  = 16B
__device__ uint4 g_t2h[N_ * 2];      // fp16 rows: 16 halves = 32B
__device__ uint4 g_t3h[N_ * 4];      // fp16 rows: 32 halves = 64B
__device__ __align__(16) float g_pos4[N_ * 4];
__device__ int g_nbrT[K_ * N_];      // TRANSPOSED: nbrT[k*N + i]
__device__ int g_idx_is64;

__device__ __forceinline__ float celu1(float x) {
    return x > 0.0f ? x : expm1f(x);
}

__device__ __forceinline__ void fmax8(float* m, uint4 u) {
    __half2* h = (__half2*)&u;
#pragma unroll
    for (int q = 0; q < 4; q++) {
        float2 f = __half22float2(h[q]);
        m[2 * q]     = fmaxf(m[2 * q], f.x);
        m[2 * q + 1] = fmaxf(m[2 * q + 1], f.y);
    }
}

__device__ __forceinline__ uint4 pack8(const float* v) {
    uint4 u;
    __half2* h = (__half2*)&u;
#pragma unroll
    for (int q = 0; q < 4; q++)
        h[q] = __floats2half2_rn(v[2 * q], v[2 * q + 1]);
    return u;
}

__device__ __forceinline__ uint2 pack4(const float* v) {
    uint2 u;
    __half2* h = (__half2*)&u;
    h[0] = __floats2half2_rn(v[0], v[1]);
    h[1] = __floats2half2_rn(v[2], v[3]);
    return u;
}

// ---------------- K0: dtype detect ----------------
__global__ void detect_kernel(const void* __restrict__ idx_raw)
{
    if (threadIdx.x == 0) {
        const long long* p = (const long long*)idx_raw;
        const long long mid = 1 << 20;
        int ok = 1;
        for (int t = 0; t < 32; t++) {
            long long v = p[mid + t];
            if (v < 0 || v >= N_) { ok = 0; break; }
        }
        g_idx_is64 = ok;
    }
}

// ---------------- K1: transpose neighbor lists to k-major ----------------
// one block per 64-point tile; smem 64x64 int tile
__global__ void __launch_bounds__(256)
transpose_kernel(const void* __restrict__ idx_raw)
{
    __shared__ int tile[64][65];
    const int tbase = blockIdx.x * 64;            // point base
    const int col = threadIdx.x & 63;             // 0..63
    const int roff = threadIdx.x >> 6;            // 0..3

    if (g_idx_is64) {
        const long long* p = (const long long*)idx_raw;
#pragma unroll
        for (int r = 0; r < 64; r += 4) {
            int row = r + roff;                   // point within tile
            tile[row][col] = ((int)p[(size_t)(tbase + row) * K_ + col]) & NM_;
        }
    } else {
        const int* p = (const int*)idx_raw;
#pragma unroll
        for (int r = 0; r < 64; r += 4) {
            int row = r + roff;
            tile[row][col] = p[(size_t)(tbase + row) * K_ + col] & NM_;
        }
    }
    __syncthreads();

#pragma unroll
    for (int kb = 0; kb < 64; kb += 4) {
        int k = kb + roff;
        g_nbrT[(size_t)k * N_ + tbase + col] = tile[col][k];
    }
}

// ---------------- K2: prep — pos4, t1, out pos copy, tail zero ----------------
__global__ void prep_kernel(const float* __restrict__ pos,
                            const float* __restrict__ w1a,
                            float* __restrict__ out, int out_size)
{
    const int stride = gridDim.x * blockDim.x;
    const int tid = blockIdx.x * blockDim.x + threadIdx.x;

    for (int i = tid; i < N_; i += stride) {
        float p0 = pos[i * 3 + 0], p1 = pos[i * 3 + 1], p2 = pos[i * 3 + 2];
        *reinterpret_cast<float4*>(g_pos4 + i * 4) = make_float4(p0, p1, p2, 0.0f);
        float t[8];
#pragma unroll
        for (int c = 0; c < 8; c++) {
            t[c] = p0 * (w1a[0 * 8 + c] + w1a[3 * 8 + c])
                 + p1 * (w1a[1 * 8 + c] + w1a[4 * 8 + c])
                 + p2 * (w1a[2 * 8 + c] + w1a[5 * 8 + c]);
        }
        g_t1h[i] = pack8(t);
    }

    for (int e = tid; e < 3 * N_; e += stride) out[e] = pos[e];
    for (int e = 35 * N_ + tid; e < out_size; e += stride) out[e] = 0.0f;
}

// ---------------- Layer 1: t1(F=8) -> t2(FN=16); 4 threads/point (K-split x4) ----------------
__global__ void __launch_bounds__(256)
layer1_kernel(const float* __restrict__ w1a, const float* __restrict__ b1a,
              const float* __restrict__ w1b, const float* __restrict__ b1b,
              const float* __restrict__ w2a)
{
    __shared__ float s_wad[24];
    __shared__ float s_ba[8];
    __shared__ float s_wb[64];
    __shared__ float s_bb[8];
    __shared__ float s_wa2[11 * 16];

    if (threadIdx.x < 24) s_wad[threadIdx.x] = w1a[24 + threadIdx.x];
    if (threadIdx.x < 8)  s_ba[threadIdx.x] = b1a[threadIdx.x];
    if (threadIdx.x < 64) s_wb[threadIdx.x] = w1b[threadIdx.x];
    if (threadIdx.x >= 64 && threadIdx.x < 72) s_bb[threadIdx.x - 64] = b1b[threadIdx.x - 64];
    if (threadIdx.x < 176) s_wa2[threadIdx.x] = w2a[threadIdx.x];
    __syncthreads();

    const int s = threadIdx.x & 3;
    const int pl = threadIdx.x >> 2;
    const int i = blockIdx.x * 64 + pl;

    const float4 pp = *reinterpret_cast<const float4*>(g_pos4 + i * 4);

    float m[8];
#pragma unroll
    for (int q = 0; q < 8; q++) m[q] = -1e30f;

    const int kbeg = s * 16;
    bool active = true;
#pragma unroll 8
    for (int kk = 0; kk < 16; kk++) {
        int k = kbeg + kk;
        int j = __ldg(g_nbrT + (size_t)k * N_ + i) & NM_;
        if (k > 0 && j == i) active = false;
        if (active) fmax8(m, __ldg(g_t1h + j));
    }
#pragma unroll
    for (int off = 1; off < 4; off <<= 1)
#pragma unroll
        for (int q = 0; q < 8; q++)
            m[q] = fmaxf(m[q], __shfl_xor_sync(0xffffffffu, m[q], off));

    float a[8];
#pragma unroll
    for (int q = 0; q < 8; q++) {
        float v = pp.x * s_wad[q] + pp.y * s_wad[8 + q] + pp.z * s_wad[16 + q];
        a[q] = celu1(m[q] - v + s_ba[q]);
    }

    float y[8];
#pragma unroll
    for (int q = 0; q < 8; q++) y[q] = s_bb[q];
#pragma unroll
    for (int in = 0; in < 8; in++)
#pragma unroll
        for (int q = 0; q < 8; q++) y[q] = fmaf(a[in], s_wb[in * 8 + q], y[q]);
#pragma unroll
    for (int q = 0; q < 8; q++) y[q] = celu1(y[q]);

    const int oc = s * 4;
    float acc[4] = {0.f, 0.f, 0.f, 0.f};
#pragma unroll
    for (int in = 0; in < 8; in++)
#pragma unroll
        for (int q = 0; q < 4; q++) acc[q] = fmaf(y[in], s_wa2[in * 16 + oc + q], acc[q]);
    float pv[3] = {pp.x, pp.y, pp.z};
#pragma unroll
    for (int d = 0; d < 3; d++)
#pragma unroll
        for (int q = 0; q < 4; q++) acc[q] = fmaf(pv[d], s_wa2[(8 + d) * 16 + oc + q], acc[q]);

    reinterpret_cast<uint2*>(g_t2h)[i * 4 + s] = pack4(acc);
}

// ---------------- Layer 2: t2(F=16) -> t3(FN=32); 4 threads/point ----------------
__global__ void __launch_bounds__(256)
layer2_kernel(const float* __restrict__ w2a, const float* __restrict__ b2a,
              const float* __restrict__ w2b, const float* __restrict__ b2b,
              const float* __restrict__ w3a)
{
    __shared__ float s_wb[256];
    __shared__ float s_wa2[19 * 32];
    __shared__ __align__(16) float s_a[64 * 17];

    if (threadIdx.x < 256) s_wb[threadIdx.x] = w2b[threadIdx.x];
    for (int k = threadIdx.x; k < 19 * 32; k += 256) s_wa2[k] = w3a[k];
    __syncthreads();

    const int s = threadIdx.x & 3;
    const int pl = threadIdx.x >> 2;
    const int i = blockIdx.x * 64 + pl;
    const int c = s & 1;
    const int h = s >> 1;

    const float4 pp = *reinterpret_cast<const float4*>(g_pos4 + i * 4);
    const float* wa_d = w2a + 8 * 16;
    float* row = s_a + pl * 17;

    float m[8];
#pragma unroll
    for (int q = 0; q < 8; q++) m[q] = -1e30f;

    const int kbeg = h * 32;
    bool active = true;
#pragma unroll 8
    for (int kk = 0; kk < 32; kk++) {
        int k = kbeg + kk;
        int j = __ldg(g_nbrT + (size_t)k * N_ + i) & NM_;
        if (k > 0 && j == i) active = false;
        if (active) fmax8(m, __ldg(g_t2h + j * 2 + c));
    }
#pragma unroll
    for (int q = 0; q < 8; q++)
        m[q] = fmaxf(m[q], __shfl_xor_sync(0xffffffffu, m[q], 2));

#pragma unroll
    for (int q = 0; q < 8; q++) row[c * 8 + q] = m[q];
    __syncwarp();

    const int col = s * 4;
    float a[4];
#pragma unroll
    for (int q = 0; q < 4; q++) {
        float mm = row[col + q];
        float v = pp.x * wa_d[col + q] + pp.y * wa_d[16 + col + q] + pp.z * wa_d[32 + col + q];
        a[q] = celu1(mm - v + b2a[col + q]);
    }
#pragma unroll
    for (int q = 0; q < 4; q++) row[col + q] = a[q];
    __syncwarp();

    float y[4];
#pragma unroll
    for (int q = 0; q < 4; q++) y[q] = b2b[col + q];
#pragma unroll
    for (int in = 0; in < 16; in++) {
        float av = row[in];
#pragma unroll
        for (int q = 0; q < 4; q++) y[q] = fmaf(av, s_wb[in * 16 + col + q], y[q]);
    }
#pragma unroll
    for (int q = 0; q < 4; q++) y[q] = celu1(y[q]);
    __syncwarp();
#pragma unroll
    for (int q = 0; q < 4; q++) row[col + q] = y[q];
    __syncwarp();

    const int oc = s * 8;
    float acc[8];
#pragma unroll
    for (int q = 0; q < 8; q++) acc[q] = 0.0f;
#pragma unroll
    for (int in = 0; in < 16; in++) {
        float yv = row[in];
#pragma unroll
        for (int q = 0; q < 8; q++) acc[q] = fmaf(yv, s_wa2[in * 32 + oc + q], acc[q]);
    }
    float pv[3] = {pp.x, pp.y, pp.z};
#pragma unroll
    for (int d = 0; d < 3; d++)
#pragma unroll
        for (int q = 0; q < 8; q++) acc[q] = fmaf(pv[d], s_wa2[(16 + d) * 32 + oc + q], acc[q]);

    g_t3h[i * 4 + s] = pack8(acc);
}

// ---------------- Layer 3: t3(F=32) -> out(fp32); 8 threads/point ----------------
__global__ void __launch_bounds__(256)
layer3_kernel(const float* __restrict__ w3a, const float* __restrict__ b3a,
              const float* __restrict__ w3b, const float* __restrict__ b3b,
              float* __restrict__ out_feat)
{
    __shared__ float s_wb[1024];
    __shared__ __align__(16) float s_a[32 * 33];

    for (int k = threadIdx.x; k < 1024; k += 256) s_wb[k] = w3b[k];
    __syncthreads();

    const int s = threadIdx.x & 7;
    const int pl = threadIdx.x >> 3;
    const int i = blockIdx.x * 32 + pl;
    const int c = s & 3;
    const int h = s >> 2;

    const float4 pp = *reinterpret_cast<const float4*>(g_pos4 + i * 4);
    const float* wa_d = w3a + 16 * 32;
    float* row = s_a + pl * 33;

    float m[8];
#pragma unroll
    for (int q = 0; q < 8; q++) m[q] = -1e30f;

    const int kbeg = h * 32;
    bool active = true;
#pragma unroll 8
    for (int kk = 0; kk < 32; kk++) {
        int k = kbeg + kk;
        int j = __ldg(g_nbrT + (size_t)k * N_ + i) & NM_;
        if (k > 0 && j == i) active = false;
        if (active) fmax8(m, __ldg(g_t3h + j * 4 + c));
    }
#pragma unroll
    for (int q = 0; q < 8; q++)
        m[q] = fmaxf(m[q], __shfl_xor_sync(0xffffffffu, m[q], 4));

#pragma unroll
    for (int q = 0; q < 8; q++) row[c * 8 + q] = m[q];
    __syncwarp();

    const int col = s * 4;
    float a[4];
#pragma unroll
    for (int q = 0; q < 4; q++) {
        float mm = row[col + q];
        float v = pp.x * wa_d[col + q] + pp.y * wa_d[32 + col + q] + pp.z * wa_d[64 + col + q];
        a[q] = celu1(mm - v + b3a[col + q]);
    }
#pragma unroll
    for (int q = 0; q < 4; q++) row[col + q] = a[q];
    __syncwarp();

    float y[4];
#pragma unroll
    for (int q = 0; q < 4; q++) y[q] = b3b[col + q];
#pragma unroll
    for (int in = 0; in < 32; in++) {
        float av = row[in];
#pragma unroll
        for (int q = 0; q < 4; q++) y[q] = fmaf(av, s_wb[in * 32 + col + q], y[q]);
    }
#pragma unroll
    for (int q = 0; q < 4; q++) y[q] = celu1(y[q]);

    *reinterpret_cast<float4*>(out_feat + (size_t)i * 32 + col) =
        make_float4(y[0], y[1], y[2], y[3]);
}

extern "C" void kernel_launch(void* const* d_in, const int* in_sizes, int n_in,
                              void* d_out, int out_size)
{
    const float* pos = (const float*)d_in[0];
    const void* in_index = d_in[4];
    const float* w1a = (const float*)d_in[5];
    const float* b1a = (const float*)d_in[6];
    const float* w1b = (const float*)d_in[7];
    const float* b1b = (const float*)d_in[8];
    const float* w2a = (const float*)d_in[9];
    const float* b2a = (const float*)d_in[10];
    const float* w2b = (const float*)d_in[11];
    const float* b2b = (const float*)d_in[12];
    const float* w3a = (const float*)d_in[13];
    const float* b3a = (const float*)d_in[14];
    const float* w3b = (const float*)d_in[15];
    const float* b3b = (const float*)d_in[16];
    float* out = (float*)d_out;

    detect_kernel<<<1, 32>>>(in_index);
    transpose_kernel<<<N_ / 64, 256>>>(in_index);
    prep_kernel<<<1024, 256>>>(pos, w1a, out, out_size);

    layer1_kernel<<<N_ / 64, 256>>>(w1a, b1a, w1b, b1b, w2a);
    layer2_kernel<<<N_ / 64, 256>>>(w2a, b2a, w2b, b2b, w3a);
    layer3_kernel<<<N_ / 32, 256>>>(w3a, b3a, w3b, b3b, out + 3 * N_);
}